// round 8
// baseline (speedup 1.0000x reference)
#include <cuda_runtime.h>

// Problem constants
#define BT     16384
#define S_DIM  256
#define O_DIM  128
#define N_DIM  32
#define NQ_DIM 64
#define NOUT   160
#define MASK_VAL (-999999.0f)
#define INV_SQRT_E 0.17677669529663687f

typedef unsigned long long ull;

// Scratch (device globals; no allocation allowed)
__device__ float g_qh[(size_t)BT * 128];   // relu(st @ Wq^T), [bt][h*32+e]
__device__ float g_v[BT];                  // bias MLP output per row
__device__ float g_p[(size_t)BT * 512];    // p[bt][h*128+o]

// ---------------- packed f32x2 helpers ----------------
static __device__ __forceinline__ ull fma2(ull a, ull b, ull c) {
    ull d;
    asm("fma.rn.f32x2 %0, %1, %2, %3;" : "=l"(d) : "l"(a), "l"(b), "l"(c));
    return d;
}
static __device__ __forceinline__ ull dup2(float w) {
    ull d;
    asm("mov.b64 %0, {%1, %1};" : "=l"(d) : "f"(w));
    return d;
}
static __device__ __forceinline__ float lo2(ull v) {
    return __uint_as_float((unsigned int)v);
}
static __device__ __forceinline__ float hi2(ull v) {
    return __uint_as_float((unsigned int)(v >> 32));
}

// ==================== K1: qh = relu([Wq;Sb_w1] @ st^T), v = MLP(st) ====================
// Column-pair scheme. BM=32 -> grid 512. Thread (lane=row ct, rt -> 10 col
// pairs). Per k: 1 LDS.32 A (per-lane) + 1 dup + 5 broadcast LDS.128 W-pairs
// + 10 fma2 = 17 instrs / 10 fma2.  Crossbar ~208B per 10 fma2.
#define K1_BM  32
#define K1_KC  32
#define K1_AS  33          // As stride (floats)
#define K1_WPS 82          // Wp row stride (u64); 82*8=656B, 16B multiple
#define K1_QS  132         // qh_s row stride (floats); 132*4=528B, 16B multiple

__global__ void __launch_bounds__(256, 3) k1_qh(
        const float* __restrict__ st,
        const float* __restrict__ Wq,
        const float* __restrict__ Sw1,
        const float* __restrict__ Sb1,
        const float* __restrict__ Sw2,
        const float* __restrict__ Sb2) {
    __shared__ __align__(16) ull   Wp[K1_KC * K1_WPS];   // [k][80 pairs] 20992B
    __shared__ float As[K1_KC * K1_AS];                  // [k][32 rows]   4224B
    __shared__ __align__(16) float qh_s[32 * K1_QS];     // transpose buf 16896B
    __shared__ float hpart[2][32];

    const int tid = threadIdx.x;
    const int rt  = tid >> 5;     // col-pair group: pairs rt*10 .. rt*10+9
    const int ct  = tid & 31;     // row within tile
    const int row0 = blockIdx.x * K1_BM;

    ull acc[10];
#pragma unroll
    for (int j = 0; j < 10; j++) acc[j] = 0ULL;

    float* wpf = (float*)Wp;

    for (int kc = 0; kc < S_DIM; kc += K1_KC) {
        __syncthreads();
        // stage A transposed: As[k][row]. 256 float4, 1/thread.
        {
            int row = tid >> 3, kq = tid & 7;
            float4 v = *(const float4*)(st + (size_t)(row0 + row) * S_DIM + kc + 4 * kq);
            As[(4 * kq + 0) * K1_AS + row] = v.x;
            As[(4 * kq + 1) * K1_AS + row] = v.y;
            As[(4 * kq + 2) * K1_AS + row] = v.z;
            As[(4 * kq + 3) * K1_AS + row] = v.w;
        }
        // stage W as adjacent-n pairs: Wp[k][n>>1] halves. 1280 float4.
        for (int i = tid; i < (NOUT * K1_KC) / 4; i += 256) {
            int n = i >> 3, kq = i & 7;
            const float* src = (n < 128) ? (Wq + n * S_DIM) : (Sw1 + (n - 128) * S_DIM);
            float4 v = *(const float4*)(src + kc + 4 * kq);
            int half = n & 1, j = n >> 1;
            wpf[((4 * kq + 0) * K1_WPS + j) * 2 + half] = v.x;
            wpf[((4 * kq + 1) * K1_WPS + j) * 2 + half] = v.y;
            wpf[((4 * kq + 2) * K1_WPS + j) * 2 + half] = v.z;
            wpf[((4 * kq + 3) * K1_WPS + j) * 2 + half] = v.w;
        }
        __syncthreads();

#pragma unroll 8
        for (int kk = 0; kk < K1_KC; kk++) {
            ull a = dup2(As[kk * K1_AS + ct]);
            const ulonglong2* wr = (const ulonglong2*)(Wp + kk * K1_WPS + rt * 10);
            ulonglong2 w01 = wr[0];
            ulonglong2 w23 = wr[1];
            ulonglong2 w45 = wr[2];
            ulonglong2 w67 = wr[3];
            ulonglong2 w89 = wr[4];
            acc[0] = fma2(a, w01.x, acc[0]);
            acc[1] = fma2(a, w01.y, acc[1]);
            acc[2] = fma2(a, w23.x, acc[2]);
            acc[3] = fma2(a, w23.y, acc[3]);
            acc[4] = fma2(a, w45.x, acc[4]);
            acc[5] = fma2(a, w45.y, acc[5]);
            acc[6] = fma2(a, w67.x, acc[6]);
            acc[7] = fma2(a, w67.y, acc[7]);
            acc[8] = fma2(a, w89.x, acc[8]);
            acc[9] = fma2(a, w89.y, acc[9]);
        }
    }

    // Epilogue: q pairs (j<64) -> qh_s (relu); hidden pairs -> bias MLP partials
    __syncthreads();   // As/Wp no longer needed; qh_s writes begin
    float hsum = 0.0f;
#pragma unroll
    for (int jj = 0; jj < 10; jj++) {
        int j = rt * 10 + jj;
        if (j < 64) {
            qh_s[ct * K1_QS + 2 * j]     = fmaxf(lo2(acc[jj]), 0.0f);
            qh_s[ct * K1_QS + 2 * j + 1] = fmaxf(hi2(acc[jj]), 0.0f);
        } else {
            int n0 = 2 * j - 128;
            hsum += fmaxf(lo2(acc[jj]) + Sb1[n0], 0.0f) * Sw2[n0]
                  + fmaxf(hi2(acc[jj]) + Sb1[n0 + 1], 0.0f) * Sw2[n0 + 1];
        }
    }
    if (rt >= 6) hpart[rt - 6][ct] = hsum;
    __syncthreads();

    // coalesced qh store: 32 rows x 32 float4 = 1024 float4, 4/thread
#pragma unroll
    for (int s = 0; s < 4; s++) {
        int i = tid + 256 * s;
        int row = i >> 5, c = i & 31;
        *(float4*)(g_qh + (size_t)(row0 + row) * 128 + 4 * c) =
            *(const float4*)(qh_s + row * K1_QS + 4 * c);
    }
    if (tid < 32)
        g_v[row0 + tid] = hpart[0][tid] + hpart[1][tid] + Sb2[0];
}

// ==================== K2: p[r][h*128+o] = sum_e qh[r][h*32+e] * Wk[h][e][o] ====================
// BM=32 -> grid 512. Wk read directly from global as adjacent-o u64 pairs.
#define K2_BM 32

__global__ void __launch_bounds__(256) k2_p(const float* __restrict__ Wk) {
    __shared__ float qh_s[K2_BM * 128];    // 16KB

    const int tid = threadIdx.x;
    const int rt  = tid >> 5;              // 8 groups of 4 rows
    const int ct  = tid & 31;              // o-pairs: ct, ct+32
    const int row0 = blockIdx.x * K2_BM;

#pragma unroll
    for (int s = 0; s < 4; s++) {
        int i = tid + 256 * s;             // 1024 float4
        ((float4*)qh_s)[i] = *(const float4*)(g_qh + (size_t)row0 * 128 + 4 * i);
    }
    __syncthreads();

    const ull* wkp = (const ull*)Wk;       // [h*32+e][64 o-pairs]
    ull* gp2 = (ull*)g_p;
#pragma unroll
    for (int h = 0; h < 4; h++) {
        ull acc[4][2];
#pragma unroll
        for (int rr = 0; rr < 4; rr++) { acc[rr][0] = 0ULL; acc[rr][1] = 0ULL; }

#pragma unroll 4
        for (int e4 = 0; e4 < 8; e4++) {
            float4 aq[4];
#pragma unroll
            for (int rr = 0; rr < 4; rr++)
                aq[rr] = *(const float4*)(qh_s + (rt * 4 + rr) * 128 + h * 32 + 4 * e4);
#pragma unroll
            for (int q = 0; q < 4; q++) {
                const ull* brow = wkp + (size_t)(h * 32 + 4 * e4 + q) * 64;
                ull b0 = brow[ct];
                ull b1 = brow[32 + ct];
#pragma unroll
                for (int rr = 0; rr < 4; rr++) {
                    float av = (q == 0) ? aq[rr].x : (q == 1) ? aq[rr].y
                             : (q == 2) ? aq[rr].z : aq[rr].w;
                    ull a = dup2(av);
                    acc[rr][0] = fma2(a, b0, acc[rr][0]);
                    acc[rr][1] = fma2(a, b1, acc[rr][1]);
                }
            }
        }
#pragma unroll
        for (int rr = 0; rr < 4; rr++) {
            size_t base = (size_t)(row0 + rt * 4 + rr) * 256 + h * 64;
            gp2[base + ct]      = acc[rr][0];
            gp2[base + 32 + ct] = acc[rr][1];
        }
    }
}

// ==================== K3: per-row scores/softmax/output (round-5 proven) ====================
__global__ void __launch_bounds__(128) k3_out(
        const float* __restrict__ z,
        const float* __restrict__ obs,
        float* __restrict__ out) {
    __shared__ float4 obf4[32 * 33];           // ob[n][c4], pad 33
    __shared__ float4 zf4[32 * 17];            // z[n][j4], pad 17
    __shared__ __align__(16) float p_s[512];
    __shared__ float part_s[4][4][32];
    __shared__ float att_s[128];
    __shared__ float w_s[32];
    __shared__ float qv_s[32];
    __shared__ float v_sh;

    const int tid = threadIdx.x;
    const size_t r = blockIdx.x;
    const float4* zr4  = (const float4*)(z + r * (size_t)(N_DIM * NQ_DIM));
    const float4* obr4 = (const float4*)(obs + r * (size_t)(N_DIM * O_DIM));

    // z load (512 float4) fused with q_vals partial sums
    float part[4];
#pragma unroll
    for (int seg = 0; seg < 4; seg++) {
        int i = tid + 128 * seg;               // i < 512
        int n = i >> 4, jq = i & 15;
        float4 v = zr4[i];
        zf4[n * 17 + jq] = v;
        part[seg] = v.x + v.y + v.z + v.w;
    }
#pragma unroll
    for (int d = 8; d > 0; d >>= 1)
#pragma unroll
        for (int seg = 0; seg < 4; seg++)
            part[seg] += __shfl_xor_sync(0xffffffffu, part[seg], d);
    if ((tid & 15) == 0) {
        int n0 = tid >> 4;
#pragma unroll
        for (int seg = 0; seg < 4; seg++)
            qv_s[n0 + 8 * seg] = part[seg] * (1.0f / 64.0f);
    }
    // obs load: 1024 float4 -> 8 segments of 128
#pragma unroll
    for (int seg = 0; seg < 8; seg++) {
        int i = tid + 128 * seg;               // i < 1024
        int n = i >> 5, c = i & 31;
        obf4[n * 33 + c] = obr4[i];
    }
    ((float4*)p_s)[tid] = ((const float4*)(g_p + r * 512))[tid];
    if (tid == 0) v_sh = g_v[r];
    __syncthreads();

    // scores: thread (n, oq) covers o-chunk [oq*32, oq*32+32)
    const int n  = tid & 31;
    const int oq = tid >> 5;
    const float4* obn = obf4 + n * 33 + oq * 8;
    const float4* pb  = (const float4*)p_s;
    float pa0 = 0.0f, pa1 = 0.0f, pa2 = 0.0f, pa3 = 0.0f;
#pragma unroll
    for (int o4 = 0; o4 < 8; o4++) {
        float4 x  = obn[o4];
        float4 p0 = pb[0  + oq * 8 + o4];
        float4 p1 = pb[32 + oq * 8 + o4];
        float4 p2 = pb[64 + oq * 8 + o4];
        float4 p3 = pb[96 + oq * 8 + o4];
        pa0 += x.x * p0.x + x.y * p0.y + x.z * p0.z + x.w * p0.w;
        pa1 += x.x * p1.x + x.y * p1.y + x.z * p1.z + x.w * p1.w;
        pa2 += x.x * p2.x + x.y * p2.y + x.z * p2.z + x.w * p2.w;
        pa3 += x.x * p3.x + x.y * p3.y + x.z * p3.z + x.w * p3.w;
    }
    part_s[oq][0][n] = pa0;
    part_s[oq][1][n] = pa1;
    part_s[oq][2][n] = pa2;
    part_s[oq][3][n] = pa3;
    __syncthreads();

    // softmax per head-warp
    const int h = tid >> 5;
    float s = part_s[0][h][n] + part_s[1][h][n] + part_s[2][h][n] + part_s[3][h][n];
    s *= INV_SQRT_E;
    if (qv_s[n] <= MASK_VAL) s = MASK_VAL;
    float m = s;
#pragma unroll
    for (int d = 16; d > 0; d >>= 1) m = fmaxf(m, __shfl_xor_sync(0xffffffffu, m, d));
    float ex = __expf(s - m);
    float ssum = ex;
#pragma unroll
    for (int d = 16; d > 0; d >>= 1) ssum += __shfl_xor_sync(0xffffffffu, ssum, d);
    att_s[h * 32 + n] = ex / ssum;
    __syncthreads();

    if (tid < 32)
        w_s[tid] = att_s[tid] + att_s[32 + tid] + att_s[64 + tid] + att_s[96 + tid] + 1e-10f;
    __syncthreads();

    if (tid < 64) {
        const float* zsf = (const float*)zf4;  // row stride 68 floats
        float acc = (float)N_DIM * v_sh;
#pragma unroll
        for (int nn = 0; nn < 32; nn++) acc = fmaf(w_s[nn], zsf[nn * 68 + tid], acc);
        out[r * 64 + tid] = acc;
    }
}

// ==================== launch ====================
extern "C" void kernel_launch(void* const* d_in, const int* in_sizes, int n_in,
                              void* d_out, int out_size) {
    (void)in_sizes; (void)n_in; (void)out_size;
    const float* z   = (const float*)d_in[0];
    const float* st  = (const float*)d_in[1];
    const float* obs = (const float*)d_in[2];
    const float* Wq  = (const float*)d_in[3];
    const float* Wk  = (const float*)d_in[4];
    const float* Sw1 = (const float*)d_in[5];
    const float* Sb1 = (const float*)d_in[6];
    const float* Sw2 = (const float*)d_in[7];
    const float* Sb2 = (const float*)d_in[8];
    float* out = (float*)d_out;

    k1_qh<<<BT / K1_BM, 256>>>(st, Wq, Sw1, Sb1, Sw2, Sb2);
    k2_p<<<BT / K2_BM, 256>>>(Wk);
    k3_out<<<BT, 128>>>(z, obs, out);
}

// round 9
// speedup vs baseline: 1.2235x; 1.2235x over previous
#include <cuda_runtime.h>

// Problem constants
#define BT     16384
#define S_DIM  256
#define O_DIM  128
#define N_DIM  32
#define NQ_DIM 64
#define NOUT   160
#define MASK_VAL (-999999.0f)
#define INV_SQRT_E 0.17677669529663687f

typedef unsigned long long ull;

// Scratch (device globals; no allocation allowed)
__device__ float g_qh[(size_t)BT * 128];   // relu(st @ Wq^T), [bt][h*32+e]
__device__ float g_v[BT];                  // bias MLP output per row
__device__ float g_p[(size_t)BT * 512];    // p[bt][h*128+o]

// ---------------- packed f32x2 helpers ----------------
static __device__ __forceinline__ ull fma2(ull a, ull b, ull c) {
    ull d;
    asm("fma.rn.f32x2 %0, %1, %2, %3;" : "=l"(d) : "l"(a), "l"(b), "l"(c));
    return d;
}
static __device__ __forceinline__ ull dup2(float w) {
    ull d;
    asm("mov.b64 %0, {%1, %1};" : "=l"(d) : "f"(w));
    return d;
}
static __device__ __forceinline__ float lo2(ull v) {
    return __uint_as_float((unsigned int)v);
}
static __device__ __forceinline__ float hi2(ull v) {
    return __uint_as_float((unsigned int)(v >> 32));
}

// ==================== K1: qh = relu([Wq;Sb_w1] @ st^T), v = MLP(st) ====================
// (round-7 proven: 43.2us) BM=64, grid 256, software-pipelined, scalar W LDS.32
// + reg dup, broadcast A LDS.64.
#define K1_BM 64
#define K1_KC 32
#define K1_AS 66                       // As stride (floats)
#define K1_WS 33                       // Ws stride (floats)
#define K1_SMEM (K1_KC*K1_AS*4 + NOUT*K1_WS*4)   // 29568B

__global__ void __launch_bounds__(256, 2) k1_qh(
        const float* __restrict__ st,
        const float* __restrict__ Wq,
        const float* __restrict__ Sw1,
        const float* __restrict__ Sb1,
        const float* __restrict__ Sw2,
        const float* __restrict__ Sb2) {
    extern __shared__ float smem[];
    float* As = smem;                          // [32 k][66]
    float* Ws = smem + K1_KC * K1_AS;          // [160 n][33]

    const int tid = threadIdx.x;
    const int rt  = tid >> 5;     // 8 groups of 8 rows
    const int ct  = tid & 31;
    const int row0 = blockIdx.x * K1_BM;

    const float* wp0 = Ws + (ct)       * K1_WS;
    const float* wp1 = Ws + (ct + 32)  * K1_WS;
    const float* wp2 = Ws + (ct + 64)  * K1_WS;
    const float* wp3 = Ws + (ct + 96)  * K1_WS;
    const float* wp4 = Ws + (ct + 128) * K1_WS;

    ull acc[4][5];
#pragma unroll
    for (int i = 0; i < 4; i++)
#pragma unroll
        for (int j = 0; j < 5; j++) acc[i][j] = 0ULL;

    for (int kc = 0; kc < S_DIM; kc += K1_KC) {
        __syncthreads();
#pragma unroll
        for (int s = 0; s < 2; s++) {
            int idx = tid + 256 * s;
            int row = idx >> 3, kq = idx & 7;
            float4 v = *(const float4*)(st + (size_t)(row0 + row) * S_DIM + kc + 4 * kq);
            As[(4 * kq + 0) * K1_AS + row] = v.x;
            As[(4 * kq + 1) * K1_AS + row] = v.y;
            As[(4 * kq + 2) * K1_AS + row] = v.z;
            As[(4 * kq + 3) * K1_AS + row] = v.w;
        }
        for (int i = tid; i < (NOUT * K1_KC) / 4; i += 256) {
            int n = i >> 3, kq = i & 7;
            const float* src = (n < 128) ? (Wq + n * S_DIM) : (Sw1 + (n - 128) * S_DIM);
            float4 v = *(const float4*)(src + kc + 4 * kq);
            Ws[n * K1_WS + 4 * kq + 0] = v.x;
            Ws[n * K1_WS + 4 * kq + 1] = v.y;
            Ws[n * K1_WS + 4 * kq + 2] = v.z;
            Ws[n * K1_WS + 4 * kq + 3] = v.w;
        }
        __syncthreads();

        float c0 = wp0[0], c1 = wp1[0], c2 = wp2[0], c3 = wp3[0], c4 = wp4[0];
        const float* ar0 = As + rt * 8;
        ull a0 = *(const ull*)(ar0);
        ull a1 = *(const ull*)(ar0 + 2);
        ull a2 = *(const ull*)(ar0 + 4);
        ull a3 = *(const ull*)(ar0 + 6);
#pragma unroll
        for (int kk = 0; kk < K1_KC; kk++) {
            float d0, d1, d2, d3, d4;
            ull e0, e1, e2, e3;
            if (kk < K1_KC - 1) {
                d0 = wp0[kk + 1]; d1 = wp1[kk + 1]; d2 = wp2[kk + 1];
                d3 = wp3[kk + 1]; d4 = wp4[kk + 1];
                const float* arn = As + (kk + 1) * K1_AS + rt * 8;
                e0 = *(const ull*)(arn);
                e1 = *(const ull*)(arn + 2);
                e2 = *(const ull*)(arn + 4);
                e3 = *(const ull*)(arn + 6);
            } else {
                d0 = d1 = d2 = d3 = d4 = 0.0f;
                e0 = e1 = e2 = e3 = 0ULL;
            }
            ull b0 = dup2(c0), b1 = dup2(c1), b2 = dup2(c2),
                b3 = dup2(c3), b4 = dup2(c4);
            acc[0][0] = fma2(a0, b0, acc[0][0]);
            acc[1][0] = fma2(a1, b0, acc[1][0]);
            acc[2][0] = fma2(a2, b0, acc[2][0]);
            acc[3][0] = fma2(a3, b0, acc[3][0]);
            acc[0][1] = fma2(a0, b1, acc[0][1]);
            acc[1][1] = fma2(a1, b1, acc[1][1]);
            acc[2][1] = fma2(a2, b1, acc[2][1]);
            acc[3][1] = fma2(a3, b1, acc[3][1]);
            acc[0][2] = fma2(a0, b2, acc[0][2]);
            acc[1][2] = fma2(a1, b2, acc[1][2]);
            acc[2][2] = fma2(a2, b2, acc[2][2]);
            acc[3][2] = fma2(a3, b2, acc[3][2]);
            acc[0][3] = fma2(a0, b3, acc[0][3]);
            acc[1][3] = fma2(a1, b3, acc[1][3]);
            acc[2][3] = fma2(a2, b3, acc[2][3]);
            acc[3][3] = fma2(a3, b3, acc[3][3]);
            acc[0][4] = fma2(a0, b4, acc[0][4]);
            acc[1][4] = fma2(a1, b4, acc[1][4]);
            acc[2][4] = fma2(a2, b4, acc[2][4]);
            acc[3][4] = fma2(a3, b4, acc[3][4]);
            c0 = d0; c1 = d1; c2 = d2; c3 = d3; c4 = d4;
            a0 = e0; a1 = e1; a2 = e2; a3 = e3;
        }
    }

    const float b1c = Sb1[ct];
    const float w2c = Sw2[ct];
    const float b2c = Sb2[0];
#pragma unroll
    for (int i = 0; i < 4; i++) {
        int r0 = row0 + rt * 8 + 2 * i;
#pragma unroll
        for (int j = 0; j < 4; j++) {
            g_qh[(size_t)r0 * 128 + ct + 32 * j]       = fmaxf(lo2(acc[i][j]), 0.0f);
            g_qh[(size_t)(r0 + 1) * 128 + ct + 32 * j] = fmaxf(hi2(acc[i][j]), 0.0f);
        }
        float h0 = fmaxf(lo2(acc[i][4]) + b1c, 0.0f) * w2c;
        float h1 = fmaxf(hi2(acc[i][4]) + b1c, 0.0f) * w2c;
#pragma unroll
        for (int d = 16; d > 0; d >>= 1) {
            h0 += __shfl_xor_sync(0xffffffffu, h0, d);
            h1 += __shfl_xor_sync(0xffffffffu, h1, d);
        }
        if (ct == 0) {
            g_v[r0]     = h0 + b2c;
            g_v[r0 + 1] = h1 + b2c;
        }
    }
}

// ==================== K2: p[r][h*128+o] = sum_e qh[r][h*32+e] * Wk[h][e][o] ====================
#define K2_BM 32

__global__ void __launch_bounds__(256) k2_p(const float* __restrict__ Wk) {
    __shared__ float qh_s[K2_BM * 128];    // 16KB

    const int tid = threadIdx.x;
    const int rt  = tid >> 5;
    const int ct  = tid & 31;
    const int row0 = blockIdx.x * K2_BM;

#pragma unroll
    for (int s = 0; s < 4; s++) {
        int i = tid + 256 * s;
        ((float4*)qh_s)[i] = *(const float4*)(g_qh + (size_t)row0 * 128 + 4 * i);
    }
    __syncthreads();

    const ull* wkp = (const ull*)Wk;
    ull* gp2 = (ull*)g_p;
#pragma unroll
    for (int h = 0; h < 4; h++) {
        ull acc[4][2];
#pragma unroll
        for (int rr = 0; rr < 4; rr++) { acc[rr][0] = 0ULL; acc[rr][1] = 0ULL; }

#pragma unroll 4
        for (int e4 = 0; e4 < 8; e4++) {
            float4 aq[4];
#pragma unroll
            for (int rr = 0; rr < 4; rr++)
                aq[rr] = *(const float4*)(qh_s + (rt * 4 + rr) * 128 + h * 32 + 4 * e4);
#pragma unroll
            for (int q = 0; q < 4; q++) {
                const ull* brow = wkp + (size_t)(h * 32 + 4 * e4 + q) * 64;
                ull b0 = brow[ct];
                ull b1 = brow[32 + ct];
#pragma unroll
                for (int rr = 0; rr < 4; rr++) {
                    float av = (q == 0) ? aq[rr].x : (q == 1) ? aq[rr].y
                             : (q == 2) ? aq[rr].z : aq[rr].w;
                    ull a = dup2(av);
                    acc[rr][0] = fma2(a, b0, acc[rr][0]);
                    acc[rr][1] = fma2(a, b1, acc[rr][1]);
                }
            }
        }
#pragma unroll
        for (int rr = 0; rr < 4; rr++) {
            size_t base = (size_t)(row0 + rt * 4 + rr) * 256 + h * 64;
            gp2[base + ct]      = acc[rr][0];
            gp2[base + 32 + ct] = acc[rr][1];
        }
    }
}

// ==================== K3 slim: no z smem; epilogue rereads z via L1 ====================
__global__ void __launch_bounds__(128) k3_out(
        const float* __restrict__ z,
        const float* __restrict__ obs,
        float* __restrict__ out) {
    __shared__ float4 obf4[32 * 33];           // 16.9KB
    __shared__ __align__(16) float p_s[512];   // 2KB
    __shared__ float part_s[4][4][32];         // 2KB
    __shared__ float att_s[128];
    __shared__ float w_s[32];
    __shared__ float qv_s[32];
    __shared__ float v_sh;

    const int tid = threadIdx.x;
    const size_t r = blockIdx.x;
    const float*  zr   = z + r * (size_t)(N_DIM * NQ_DIM);
    const float4* zr4  = (const float4*)zr;
    const float4* obr4 = (const float4*)(obs + r * (size_t)(N_DIM * O_DIM));

    // z pass: q_vals only (no smem store); populates L1 for the epilogue reread
    float part[4];
#pragma unroll
    for (int seg = 0; seg < 4; seg++) {
        int i = tid + 128 * seg;               // i < 512; n = i>>4
        float4 v = zr4[i];
        part[seg] = v.x + v.y + v.z + v.w;
    }
#pragma unroll
    for (int d = 8; d > 0; d >>= 1)
#pragma unroll
        for (int seg = 0; seg < 4; seg++)
            part[seg] += __shfl_xor_sync(0xffffffffu, part[seg], d);
    if ((tid & 15) == 0) {
        int n0 = tid >> 4;
#pragma unroll
        for (int seg = 0; seg < 4; seg++)
            qv_s[n0 + 8 * seg] = part[seg] * (1.0f / 64.0f);
    }
    // obs load: 1024 float4 -> 8 segments of 128
#pragma unroll
    for (int seg = 0; seg < 8; seg++) {
        int i = tid + 128 * seg;
        int n = i >> 5, c = i & 31;
        obf4[n * 33 + c] = obr4[i];
    }
    ((float4*)p_s)[tid] = ((const float4*)(g_p + r * 512))[tid];
    if (tid == 0) v_sh = g_v[r];
    __syncthreads();

    // scores: thread (n, oq) covers o-chunk [oq*32, oq*32+32)
    const int n  = tid & 31;
    const int oq = tid >> 5;
    const float4* obn = obf4 + n * 33 + oq * 8;
    const float4* pb  = (const float4*)p_s;
    float pa0 = 0.0f, pa1 = 0.0f, pa2 = 0.0f, pa3 = 0.0f;
#pragma unroll
    for (int o4 = 0; o4 < 8; o4++) {
        float4 x  = obn[o4];
        float4 p0 = pb[0  + oq * 8 + o4];
        float4 p1 = pb[32 + oq * 8 + o4];
        float4 p2 = pb[64 + oq * 8 + o4];
        float4 p3 = pb[96 + oq * 8 + o4];
        pa0 += x.x * p0.x + x.y * p0.y + x.z * p0.z + x.w * p0.w;
        pa1 += x.x * p1.x + x.y * p1.y + x.z * p1.z + x.w * p1.w;
        pa2 += x.x * p2.x + x.y * p2.y + x.z * p2.z + x.w * p2.w;
        pa3 += x.x * p3.x + x.y * p3.y + x.z * p3.z + x.w * p3.w;
    }
    part_s[oq][0][n] = pa0;
    part_s[oq][1][n] = pa1;
    part_s[oq][2][n] = pa2;
    part_s[oq][3][n] = pa3;
    __syncthreads();

    // softmax per head-warp
    const int h = tid >> 5;
    float s = part_s[0][h][n] + part_s[1][h][n] + part_s[2][h][n] + part_s[3][h][n];
    s *= INV_SQRT_E;
    if (qv_s[n] <= MASK_VAL) s = MASK_VAL;
    float m = s;
#pragma unroll
    for (int d = 16; d > 0; d >>= 1) m = fmaxf(m, __shfl_xor_sync(0xffffffffu, m, d));
    float ex = __expf(s - m);
    float ssum = ex;
#pragma unroll
    for (int d = 16; d > 0; d >>= 1) ssum += __shfl_xor_sync(0xffffffffu, ssum, d);
    att_s[h * 32 + n] = ex / ssum;
    __syncthreads();

    if (tid < 32)
        w_s[tid] = att_s[tid] + att_s[32 + tid] + att_s[64 + tid] + att_s[96 + tid] + 1e-10f;
    __syncthreads();

    if (tid < 64) {                            // z reread: L1 hits (just loaded)
        float acc = (float)N_DIM * v_sh;
#pragma unroll
        for (int nn = 0; nn < 32; nn++)
            acc = fmaf(w_s[nn], __ldg(zr + nn * 64 + tid), acc);
        out[r * 64 + tid] = acc;
    }
}

// ==================== launch ====================
extern "C" void kernel_launch(void* const* d_in, const int* in_sizes, int n_in,
                              void* d_out, int out_size) {
    (void)in_sizes; (void)n_in; (void)out_size;
    const float* z   = (const float*)d_in[0];
    const float* st  = (const float*)d_in[1];
    const float* obs = (const float*)d_in[2];
    const float* Wq  = (const float*)d_in[3];
    const float* Wk  = (const float*)d_in[4];
    const float* Sw1 = (const float*)d_in[5];
    const float* Sb1 = (const float*)d_in[6];
    const float* Sw2 = (const float*)d_in[7];
    const float* Sb2 = (const float*)d_in[8];
    float* out = (float*)d_out;

    cudaFuncSetAttribute(k1_qh, cudaFuncAttributeMaxDynamicSharedMemorySize, K1_SMEM);

    k1_qh<<<BT / K1_BM, 256, K1_SMEM>>>(st, Wq, Sw1, Sb1, Sw2, Sb2);
    k2_p<<<BT / K2_BM, 256>>>(Wk);
    k3_out<<<BT, 128>>>(z, obs, out);
}